// round 14
// baseline (speedup 1.0000x reference)
#include <cuda_runtime.h>
#include <cuda_bf16.h>
#include <math.h>
#include <stdint.h>

// ---------------- problem dims ----------------
#define BB    4
#define SS    4096
#define HH    2048
#define VV    32000
#define IDIM  64
#define NLC   8192
#define NROWS (BB * SS)          // 16384
#define K2    192                // split-K concat: A=[hi|hi|lo], B=[hi|lo|hi]
#define NB_PREP 148

// ---------------- device scratch ----------------
__device__ int g_winner[NROWS];
__device__ int g_slot[NROWS];
__device__ int g_widx[NROWS];
__device__ int g_count;
__device__ unsigned g_bar1 = 0, g_bar2 = 0;
__device__ int g_prep_done = 0;
__device__ __align__(16) __nv_bfloat16 g_a2 [NLC * K2];   // activations, K-concat split
__device__ __align__(16) __nv_bfloat16 g_b2T[HH * K2];    // Wout^T, K-concat split, [n][k]

// ---------------- helpers ----------------
__device__ __forceinline__ float gelu_exact(float x) {
    return 0.5f * x * (1.0f + erff(x * 0.70710678118654752440f));
}
__device__ __forceinline__ float2 ffma2(float2 a, float2 b, float2 c) {
    unsigned long long ra, rb, rc, rd;
    ra = *reinterpret_cast<unsigned long long*>(&a);
    rb = *reinterpret_cast<unsigned long long*>(&b);
    rc = *reinterpret_cast<unsigned long long*>(&c);
    asm("fma.rn.f32x2 %0, %1, %2, %3;" : "=l"(rd) : "l"(ra), "l"(rb), "l"(rc));
    return *reinterpret_cast<float2*>(&rd);
}
__device__ __forceinline__ uint32_t smem_u32(const void* p) {
    uint32_t a;
    asm("{ .reg .u64 t; cvta.to.shared.u64 t, %1; cvt.u32.u64 %0, t; }" : "=r"(a) : "l"(p));
    return a;
}
__device__ __forceinline__ void ldm_x4(uint32_t* r, uint32_t addr) {
    asm volatile("ldmatrix.sync.aligned.m8n8.x4.shared.b16 {%0,%1,%2,%3}, [%4];"
        : "=r"(r[0]), "=r"(r[1]), "=r"(r[2]), "=r"(r[3]) : "r"(addr));
}
__device__ __forceinline__ void mma16816(float* c, const uint32_t* a, uint32_t b0, uint32_t b1) {
    asm volatile("mma.sync.aligned.m16n8k16.row.col.f32.bf16.bf16.f32 "
        "{%0,%1,%2,%3}, {%4,%5,%6,%7}, {%8,%9}, {%0,%1,%2,%3};"
        : "+f"(c[0]), "+f"(c[1]), "+f"(c[2]), "+f"(c[3])
        : "r"(a[0]), "r"(a[1]), "r"(a[2]), "r"(a[3]), "r"(b0), "r"(b1));
}

// grid barrier for a resident 148-block grid
__device__ __forceinline__ void grid_bar(unsigned* bar) {
    __syncthreads();
    __threadfence();
    if (threadIdx.x == 0) {
        atomicAdd(bar, 1u);
        while (atomicAdd(bar, 0u) < NB_PREP) { }
    }
    __syncthreads();
    __threadfence();
}

// ---------------- kernel 1: fused init + winner + compact ----------------
__global__ void __launch_bounds__(256) k_prep(const int* __restrict__ pos_b,
                                              const int* __restrict__ pos_s) {
    const int gt = blockIdx.x * 256 + threadIdx.x;

    if (gt < NROWS) g_winner[gt] = -1;
    if (gt == 0) g_count = 0;
    grid_bar(&g_bar1);

    if (gt < NLC) {
        int slot = pos_b[gt] * SS + pos_s[gt];
        atomicMax(&g_winner[slot], gt);     // JAX scatter: last update wins
    }
    grid_bar(&g_bar2);

    if (gt < NROWS) {
        int w = g_winner[gt];
        if (w >= 0) {
            int p = atomicAdd(&g_count, 1);
            g_slot[p] = gt;
            g_widx[p] = w;
        }
    }

    // self-reset for deterministic graph replay
    __syncthreads();
    if (threadIdx.x == 0) {
        int v = atomicAdd(&g_prep_done, 1);
        if (v == NB_PREP - 1) {
            g_bar1 = 0; g_bar2 = 0; g_prep_done = 0;
            __threadfence();
        }
    }
}

// ---------------- kernel 2: MLP (bids 0-255) + coalesced Wout split (bids 256-287) ----
#define MLP_E 32
__global__ void __launch_bounds__(256) k_aux(const float* __restrict__ lc,
                      const float* __restrict__ W0, const float* __restrict__ b0,
                      const float* __restrict__ W1, const float* __restrict__ b1,
                      const float* __restrict__ W2, const float* __restrict__ b2,
                      const float* __restrict__ Wout) {
    const int tid = threadIdx.x;

    if (blockIdx.x >= 256) {
        // ---- Wout split+transpose via smem tile: coalesced reads, tiled writes ----
        __shared__ float tile[IDIM][65];             // [k][n_local], stride 65 = conflict-free
        const int n0 = (blockIdx.x - 256) * 64;

        // load Wout[0:64][n0:n0+64]: thread t -> row t>>2, quads (t&3)+4i (coalesced 64B/4thr)
        {
            int r = tid >> 2, q = tid & 3;
            #pragma unroll
            for (int i = 0; i < 4; i++) {
                float4 v = *reinterpret_cast<const float4*>(Wout + r * HH + n0 + (q + 4 * i) * 4);
                int c = (q + 4 * i) * 4;
                tile[r][c + 0] = v.x; tile[r][c + 1] = v.y;
                tile[r][c + 2] = v.z; tile[r][c + 3] = v.w;
            }
        }
        __syncthreads();

        // write g_b2T[n][k]: thread t -> n = n0 + t>>2, k-quad (t&3)*16; 32B contiguous stores
        {
            int nl = tid >> 2, kq = (tid & 3) * 16;
            __nv_bfloat16 h[16], l[16];
            #pragma unroll
            for (int j = 0; j < 16; j++) {
                float w = tile[kq + j][nl];
                h[j] = __float2bfloat16(w);
                l[j] = __float2bfloat16(w - __bfloat162float(h[j]));
            }
            size_t rb = (size_t)(n0 + nl) * K2;
            uint4* ph = reinterpret_cast<uint4*>(h);
            uint4* pl = reinterpret_cast<uint4*>(l);
            // [0,64)=hi, [64,128)=lo, [128,192)=hi  (pairs with A's hi,hi,lo)
            *reinterpret_cast<uint4*>(&g_b2T[rb +       kq])     = ph[0];
            *reinterpret_cast<uint4*>(&g_b2T[rb +       kq + 8]) = ph[1];
            *reinterpret_cast<uint4*>(&g_b2T[rb +  64 + kq])     = pl[0];
            *reinterpret_cast<uint4*>(&g_b2T[rb +  64 + kq + 8]) = pl[1];
            *reinterpret_cast<uint4*>(&g_b2T[rb + 128 + kq])     = ph[0];
            *reinterpret_cast<uint4*>(&g_b2T[rb + 128 + kq + 8]) = ph[1];
        }
        return;
    }

    // ---- MLP 1->64->64->64, emit K-concat split-bf16: [hi | hi | lo] ----
    __shared__ float AT[IDIM][MLP_E + 2];
    __shared__ float Wsh[IDIM * IDIM];
    __shared__ float xsh[MLP_E];

    const int f4  = tid & 15;
    const int eg  = tid >> 4;
    const int j0  = f4 * 4;
    const int e0  = blockIdx.x * MLP_E;

    if (tid < MLP_E) xsh[tid] = lc[e0 + tid];
    {
        const float4* src = reinterpret_cast<const float4*>(W1);
        float4* dst = reinterpret_cast<float4*>(Wsh);
        #pragma unroll
        for (int i = 0; i < 4; i++) dst[tid + 256 * i] = src[tid + 256 * i];
    }
    __syncthreads();

    #pragma unroll
    for (int r = 0; r < 4; r++) {
        int k = j0 + r;
        float w = W0[k], b = b0[k];
        float v0 = gelu_exact(fmaf(xsh[2 * eg],     w, b));
        float v1 = gelu_exact(fmaf(xsh[2 * eg + 1], w, b));
        *reinterpret_cast<float2*>(&AT[k][2 * eg]) = make_float2(v0, v1);
    }
    __syncthreads();

    float2 acc[4];
    {
        float4 bb = *reinterpret_cast<const float4*>(b1 + j0);
        acc[0] = make_float2(bb.x, bb.x); acc[1] = make_float2(bb.y, bb.y);
        acc[2] = make_float2(bb.z, bb.z); acc[3] = make_float2(bb.w, bb.w);
        #pragma unroll 8
        for (int k = 0; k < IDIM; k++) {
            float2 a2 = *reinterpret_cast<float2*>(&AT[k][2 * eg]);
            float4 w4 = *reinterpret_cast<float4*>(&Wsh[k * IDIM + j0]);
            acc[0] = ffma2(a2, make_float2(w4.x, w4.x), acc[0]);
            acc[1] = ffma2(a2, make_float2(w4.y, w4.y), acc[1]);
            acc[2] = ffma2(a2, make_float2(w4.z, w4.z), acc[2]);
            acc[3] = ffma2(a2, make_float2(w4.w, w4.w), acc[3]);
        }
    }
    __syncthreads();

    #pragma unroll
    for (int f = 0; f < 4; f++) {
        *reinterpret_cast<float2*>(&AT[j0 + f][2 * eg]) =
            make_float2(gelu_exact(acc[f].x), gelu_exact(acc[f].y));
    }
    {
        const float4* src = reinterpret_cast<const float4*>(W2);
        float4* dst = reinterpret_cast<float4*>(Wsh);
        #pragma unroll
        for (int i = 0; i < 4; i++) dst[tid + 256 * i] = src[tid + 256 * i];
    }
    __syncthreads();

    {
        float4 bb = *reinterpret_cast<const float4*>(b2 + j0);
        acc[0] = make_float2(bb.x, bb.x); acc[1] = make_float2(bb.y, bb.y);
        acc[2] = make_float2(bb.z, bb.z); acc[3] = make_float2(bb.w, bb.w);
        #pragma unroll 8
        for (int k = 0; k < IDIM; k++) {
            float2 a2 = *reinterpret_cast<float2*>(&AT[k][2 * eg]);
            float4 w4 = *reinterpret_cast<float4*>(&Wsh[k * IDIM + j0]);
            acc[0] = ffma2(a2, make_float2(w4.x, w4.x), acc[0]);
            acc[1] = ffma2(a2, make_float2(w4.y, w4.y), acc[1]);
            acc[2] = ffma2(a2, make_float2(w4.z, w4.z), acc[2]);
            acc[3] = ffma2(a2, make_float2(w4.w, w4.w), acc[3]);
        }
    }

    #pragma unroll
    for (int half = 0; half < 2; half++) {
        float v[4];
        v[0] = gelu_exact(half ? acc[0].y : acc[0].x);
        v[1] = gelu_exact(half ? acc[1].y : acc[1].x);
        v[2] = gelu_exact(half ? acc[2].y : acc[2].x);
        v[3] = gelu_exact(half ? acc[3].y : acc[3].x);
        __nv_bfloat16 h[4], l[4];
        #pragma unroll
        for (int f = 0; f < 4; f++) {
            h[f] = __float2bfloat16(v[f]);
            l[f] = __float2bfloat16(v[f] - __bfloat162float(h[f]));
        }
        size_t rb = (size_t)(e0 + 2 * eg + half) * K2;
        uint2 hb = *reinterpret_cast<uint2*>(h);
        uint2 lb = *reinterpret_cast<uint2*>(l);
        *reinterpret_cast<uint2*>(&g_a2[rb +       j0]) = hb;
        *reinterpret_cast<uint2*>(&g_a2[rb +  64 + j0]) = hb;
        *reinterpret_cast<uint2*>(&g_a2[rb + 128 + j0]) = lb;
    }
}

// ---------------- kernel 3: embedding gather (8 blocks/SM) ----------------
#define EMBED_BLOCKS 1184
__global__ void __launch_bounds__(256) k_embed(const int* __restrict__ ids,
                                               const float* __restrict__ wte,
                                               float* __restrict__ out) {
    const int lane   = threadIdx.x & 31;
    const int warp   = (blockIdx.x * blockDim.x + threadIdx.x) >> 5;
    const int nwarps = (EMBED_BLOCKS * 256) >> 5;

    for (int row = warp; row < NROWS; row += nwarps) {
        if (g_winner[row] >= 0) continue;       // overwritten by gemm epilogue
        int id = ids[row];
        id = max(0, min(id, VV - 1));
        const float4* __restrict__ src = reinterpret_cast<const float4*>(wte + (size_t)id * HH);
        float4*       __restrict__ dst = reinterpret_cast<float4*>(out + (size_t)row * HH);
        #pragma unroll
        for (int h = 0; h < 2; h++) {
            float4 v[8];
            #pragma unroll
            for (int i = 0; i < 8; i++) v[i] = src[lane + 32 * (8 * h + i)];
            #pragma unroll
            for (int i = 0; i < 8; i++) __stcs(&dst[lane + 32 * (8 * h + i)], v[i]);
        }
    }
}

// ---------------- kernel 4: HMMA GEMM [count x 192] @ [192 x 2048] + scatter ----------
// Tile 128m x 128n x 192k, smem-staged, ldmatrix.x4 fragments (validated in R12).
#define GS_STRIDE 200
#define GEMM_SMEM (2 * 128 * GS_STRIDE * 2)   // 102400 B
extern __shared__ __nv_bfloat16 gsm2[];

__global__ void __launch_bounds__(256) k_gemm_mma(const float* __restrict__ bout,
                                                  float* __restrict__ out) {
    const int count = g_count;
    const int m0 = blockIdx.y * 128;
    if (m0 >= count) return;
    const int n0 = blockIdx.x * 128;
    const int tid = threadIdx.x;

    __nv_bfloat16* As = gsm2;
    __nv_bfloat16* Bs = gsm2 + 128 * GS_STRIDE;

    // stage A (gathered rows) and B: thread t -> row t>>1, half t&1, 12 uint4 each
    {
        int r = tid >> 1, h = tid & 1;
        int row = m0 + r;
        const uint4* srcA = nullptr;
        if (row < count)
            srcA = reinterpret_cast<const uint4*>(g_a2 + (size_t)g_widx[row] * K2) + h * 12;
        uint4* dstA = reinterpret_cast<uint4*>(As + r * GS_STRIDE + h * 96);
        const uint4* srcB = reinterpret_cast<const uint4*>(g_b2T + (size_t)(n0 + r) * K2) + h * 12;
        uint4* dstB = reinterpret_cast<uint4*>(Bs + r * GS_STRIDE + h * 96);
        #pragma unroll
        for (int c = 0; c < 12; c++) {
            dstA[c] = srcA ? srcA[c] : make_uint4(0u, 0u, 0u, 0u);
            dstB[c] = srcB[c];
        }
    }
    __syncthreads();

    const int wid  = tid >> 5;
    const int lane = tid & 31;
    const int mg   = wid & 3;
    const int ng   = wid >> 2;

    uint32_t aAddr = smem_u32(As) +
        (uint32_t)(((mg * 32 + (lane & 15)) * GS_STRIDE + (lane >> 4) * 8) * 2);
    uint32_t bAddr = smem_u32(Bs) +
        (uint32_t)(((ng * 64 + (lane & 7) + ((lane >> 4) << 3)) * GS_STRIDE +
                    (((lane >> 3) & 1) << 3)) * 2);

    float acc[2][8][4];
    #pragma unroll
    for (int am = 0; am < 2; am++)
        #pragma unroll
        for (int ns = 0; ns < 8; ns++)
            #pragma unroll
            for (int c = 0; c < 4; c++) acc[am][ns][c] = 0.f;

    #pragma unroll 1
    for (int ks = 0; ks < K2 / 16; ks++) {
        uint32_t aF0[4], aF1[4], bF[4][4];
        ldm_x4(aF0, aAddr);
        ldm_x4(aF1, aAddr + 16 * GS_STRIDE * 2);
        #pragma unroll
        for (int p = 0; p < 4; p++) ldm_x4(bF[p], bAddr + p * 16 * GS_STRIDE * 2);
        aAddr += 32;
        bAddr += 32;
        #pragma unroll
        for (int p = 0; p < 4; p++) {
            mma16816(acc[0][2 * p],     aF0, bF[p][0], bF[p][1]);
            mma16816(acc[0][2 * p + 1], aF0, bF[p][2], bF[p][3]);
            mma16816(acc[1][2 * p],     aF1, bF[p][0], bF[p][1]);
            mma16816(acc[1][2 * p + 1], aF1, bF[p][2], bF[p][3]);
        }
    }

    // epilogue: scatter rows via g_slot, add bias
    #pragma unroll
    for (int am = 0; am < 2; am++) {
        int r = m0 + mg * 32 + am * 16 + (lane >> 2);
        int s0 = (r     < count) ? g_slot[r]     : -1;
        int s1 = (r + 8 < count) ? g_slot[r + 8] : -1;
        #pragma unroll
        for (int ns = 0; ns < 8; ns++) {
            int col = n0 + ng * 64 + ns * 8 + (lane & 3) * 2;
            float2 bv = *reinterpret_cast<const float2*>(bout + col);
            if (s0 >= 0) {
                float2 v = make_float2(acc[am][ns][0] + bv.x, acc[am][ns][1] + bv.y);
                *reinterpret_cast<float2*>(out + (size_t)s0 * HH + col) = v;
            }
            if (s1 >= 0) {
                float2 v = make_float2(acc[am][ns][2] + bv.x, acc[am][ns][3] + bv.y);
                *reinterpret_cast<float2*>(out + (size_t)s1 * HH + col) = v;
            }
        }
    }
}

// ---------------- one-time smem opt-in ----------------
namespace {
struct HxInit {
    HxInit() {
        cudaFuncSetAttribute(k_gemm_mma, cudaFuncAttributeMaxDynamicSharedMemorySize, GEMM_SMEM);
    }
};
HxInit hx_init_;
}

// ---------------- launcher: 4 nodes, single stream ----------------
extern "C" void kernel_launch(void* const* d_in, const int* in_sizes, int n_in,
                              void* d_out, int out_size) {
    const int*   input_ids = (const int*)  d_in[0];
    const float* lc        = (const float*)d_in[1];
    const int*   pos_b     = (const int*)  d_in[2];
    const int*   pos_s     = (const int*)  d_in[3];
    const float* wte       = (const float*)d_in[4];
    const float* W0        = (const float*)d_in[5];
    const float* b0        = (const float*)d_in[6];
    const float* W1        = (const float*)d_in[7];
    const float* b1        = (const float*)d_in[8];
    const float* W2        = (const float*)d_in[9];
    const float* b2        = (const float*)d_in[10];
    const float* Wout      = (const float*)d_in[11];
    const float* bout      = (const float*)d_in[12];
    float* out = (float*)d_out;

    k_aux <<<288, 256>>>(lc, W0, b0, W1, b1, W2, b2, Wout);
    k_prep<<<NB_PREP, 256>>>(pos_b, pos_s);
    k_embed<<<EMBED_BLOCKS, 256>>>(input_ids, wte, out);
    k_gemm_mma<<<dim3(HH / 128, NLC / 128), 256, GEMM_SMEM>>>(bout, out);
}

// round 15
// speedup vs baseline: 1.0963x; 1.0963x over previous
#include <cuda_runtime.h>
#include <cuda_bf16.h>
#include <math.h>
#include <stdint.h>

// ---------------- problem dims ----------------
#define BB    4
#define SS    4096
#define HH    2048
#define VV    32000
#define IDIM  64
#define NLC   8192
#define NROWS (BB * SS)          // 16384
#define K2    192                // split-K concat: A=[hi|hi|lo], B=[hi|lo|hi]
#define NB_PREP 148

// ---------------- device scratch ----------------
__device__ int g_winner[NROWS];
__device__ int g_slot[NROWS];
__device__ int g_widx[NROWS];
__device__ int g_count;
__device__ unsigned g_bar1 = 0, g_bar2 = 0;
__device__ int g_prep_done = 0;
__device__ __align__(16) __nv_bfloat16 g_a2 [NLC * K2];   // activations, K-concat split
__device__ __align__(16) __nv_bfloat16 g_b2T[HH * K2];    // Wout^T, K-concat split, [n][k]

// ---------------- helpers ----------------
__device__ __forceinline__ float gelu_exact(float x) {
    return 0.5f * x * (1.0f + erff(x * 0.70710678118654752440f));
}
__device__ __forceinline__ float2 ffma2(float2 a, float2 b, float2 c) {
    unsigned long long ra, rb, rc, rd;
    ra = *reinterpret_cast<unsigned long long*>(&a);
    rb = *reinterpret_cast<unsigned long long*>(&b);
    rc = *reinterpret_cast<unsigned long long*>(&c);
    asm("fma.rn.f32x2 %0, %1, %2, %3;" : "=l"(rd) : "l"(ra), "l"(rb), "l"(rc));
    return *reinterpret_cast<float2*>(&rd);
}
__device__ __forceinline__ uint32_t smem_u32(const void* p) {
    uint32_t a;
    asm("{ .reg .u64 t; cvta.to.shared.u64 t, %1; cvt.u32.u64 %0, t; }" : "=r"(a) : "l"(p));
    return a;
}
__device__ __forceinline__ void ldm_x4(uint32_t* r, uint32_t addr) {
    asm volatile("ldmatrix.sync.aligned.m8n8.x4.shared.b16 {%0,%1,%2,%3}, [%4];"
        : "=r"(r[0]), "=r"(r[1]), "=r"(r[2]), "=r"(r[3]) : "r"(addr));
}
__device__ __forceinline__ void mma16816(float* c, const uint32_t* a, uint32_t b0, uint32_t b1) {
    asm volatile("mma.sync.aligned.m16n8k16.row.col.f32.bf16.bf16.f32 "
        "{%0,%1,%2,%3}, {%4,%5,%6,%7}, {%8,%9}, {%0,%1,%2,%3};"
        : "+f"(c[0]), "+f"(c[1]), "+f"(c[2]), "+f"(c[3])
        : "r"(a[0]), "r"(a[1]), "r"(a[2]), "r"(a[3]), "r"(b0), "r"(b1));
}

// grid barrier among the NB_PREP prep-role blocks (bids 0..147, wave-1 resident)
__device__ __forceinline__ void grid_bar(unsigned* bar) {
    __syncthreads();
    __threadfence();
    if (threadIdx.x == 0) {
        atomicAdd(bar, 1u);
        while (atomicAdd(bar, 0u) < NB_PREP) { }
    }
    __syncthreads();
    __threadfence();
}

// ---------------- kernel 1: fused prep (bids 0-147) + MLP (148-403) + wsplit (404-435) ----
#define MLP_E 32
struct MlpSmem { float AT[IDIM][MLP_E + 2]; float Wsh[IDIM * IDIM]; float xsh[MLP_E]; };
struct WspSmem { float tile[IDIM][65]; };

__global__ void __launch_bounds__(256) k_auxprep(
                      const int* __restrict__ pos_b, const int* __restrict__ pos_s,
                      const float* __restrict__ lc,
                      const float* __restrict__ W0, const float* __restrict__ b0,
                      const float* __restrict__ W1, const float* __restrict__ b1,
                      const float* __restrict__ W2, const float* __restrict__ b2,
                      const float* __restrict__ Wout) {
    __shared__ __align__(16) char shraw[sizeof(MlpSmem)];
    const int tid = threadIdx.x;
    const int bid = blockIdx.x;

    if (bid < NB_PREP) {
        // ===== PREP role: init + winner + compact (resident-grid barrier) =====
        const int gt = bid * 256 + tid;

        if (gt < NROWS) g_winner[gt] = -1;
        if (gt == 0) g_count = 0;
        grid_bar(&g_bar1);

        if (gt < NLC) {
            int slot = pos_b[gt] * SS + pos_s[gt];
            atomicMax(&g_winner[slot], gt);     // JAX scatter: last update wins
        }
        grid_bar(&g_bar2);

        if (gt < NROWS) {
            int w = g_winner[gt];
            if (w >= 0) {
                int p = atomicAdd(&g_count, 1);
                g_slot[p] = gt;
                g_widx[p] = w;
            }
        }

        // self-reset for deterministic graph replay
        __syncthreads();
        if (tid == 0) {
            int v = atomicAdd(&g_prep_done, 1);
            if (v == NB_PREP - 1) {
                g_bar1 = 0; g_bar2 = 0; g_prep_done = 0;
                __threadfence();
            }
        }
        return;
    }

    if (bid >= NB_PREP + 256) {
        // ===== WSPLIT role: coalesced Wout split+transpose via smem tile =====
        WspSmem* S = reinterpret_cast<WspSmem*>(shraw);
        const int n0 = (bid - NB_PREP - 256) * 64;

        {
            int r = tid >> 2, q = tid & 3;
            #pragma unroll
            for (int i = 0; i < 4; i++) {
                float4 v = *reinterpret_cast<const float4*>(Wout + r * HH + n0 + (q + 4 * i) * 4);
                int c = (q + 4 * i) * 4;
                S->tile[r][c + 0] = v.x; S->tile[r][c + 1] = v.y;
                S->tile[r][c + 2] = v.z; S->tile[r][c + 3] = v.w;
            }
        }
        __syncthreads();

        {
            int nl = tid >> 2, kq = (tid & 3) * 16;
            __nv_bfloat16 h[16], l[16];
            #pragma unroll
            for (int j = 0; j < 16; j++) {
                float w = S->tile[kq + j][nl];
                h[j] = __float2bfloat16(w);
                l[j] = __float2bfloat16(w - __bfloat162float(h[j]));
            }
            size_t rb = (size_t)(n0 + nl) * K2;
            uint4* ph = reinterpret_cast<uint4*>(h);
            uint4* pl = reinterpret_cast<uint4*>(l);
            // [0,64)=hi, [64,128)=lo, [128,192)=hi  (pairs with A's hi,hi,lo)
            *reinterpret_cast<uint4*>(&g_b2T[rb +       kq])     = ph[0];
            *reinterpret_cast<uint4*>(&g_b2T[rb +       kq + 8]) = ph[1];
            *reinterpret_cast<uint4*>(&g_b2T[rb +  64 + kq])     = pl[0];
            *reinterpret_cast<uint4*>(&g_b2T[rb +  64 + kq + 8]) = pl[1];
            *reinterpret_cast<uint4*>(&g_b2T[rb + 128 + kq])     = ph[0];
            *reinterpret_cast<uint4*>(&g_b2T[rb + 128 + kq + 8]) = ph[1];
        }
        return;
    }

    // ===== MLP role: 1->64->64->64, emit K-concat split-bf16 [hi | hi | lo] =====
    MlpSmem* S = reinterpret_cast<MlpSmem*>(shraw);
    const int f4  = tid & 15;
    const int eg  = tid >> 4;
    const int j0  = f4 * 4;
    const int e0  = (bid - NB_PREP) * MLP_E;

    if (tid < MLP_E) S->xsh[tid] = lc[e0 + tid];
    {
        const float4* src = reinterpret_cast<const float4*>(W1);
        float4* dst = reinterpret_cast<float4*>(S->Wsh);
        #pragma unroll
        for (int i = 0; i < 4; i++) dst[tid + 256 * i] = src[tid + 256 * i];
    }
    __syncthreads();

    #pragma unroll
    for (int r = 0; r < 4; r++) {
        int k = j0 + r;
        float w = W0[k], b = b0[k];
        float v0 = gelu_exact(fmaf(S->xsh[2 * eg],     w, b));
        float v1 = gelu_exact(fmaf(S->xsh[2 * eg + 1], w, b));
        *reinterpret_cast<float2*>(&S->AT[k][2 * eg]) = make_float2(v0, v1);
    }
    __syncthreads();

    float2 acc[4];
    {
        float4 bb = *reinterpret_cast<const float4*>(b1 + j0);
        acc[0] = make_float2(bb.x, bb.x); acc[1] = make_float2(bb.y, bb.y);
        acc[2] = make_float2(bb.z, bb.z); acc[3] = make_float2(bb.w, bb.w);
        #pragma unroll 8
        for (int k = 0; k < IDIM; k++) {
            float2 a2 = *reinterpret_cast<float2*>(&S->AT[k][2 * eg]);
            float4 w4 = *reinterpret_cast<float4*>(&S->Wsh[k * IDIM + j0]);
            acc[0] = ffma2(a2, make_float2(w4.x, w4.x), acc[0]);
            acc[1] = ffma2(a2, make_float2(w4.y, w4.y), acc[1]);
            acc[2] = ffma2(a2, make_float2(w4.z, w4.z), acc[2]);
            acc[3] = ffma2(a2, make_float2(w4.w, w4.w), acc[3]);
        }
    }
    __syncthreads();

    #pragma unroll
    for (int f = 0; f < 4; f++) {
        *reinterpret_cast<float2*>(&S->AT[j0 + f][2 * eg]) =
            make_float2(gelu_exact(acc[f].x), gelu_exact(acc[f].y));
    }
    {
        const float4* src = reinterpret_cast<const float4*>(W2);
        float4* dst = reinterpret_cast<float4*>(S->Wsh);
        #pragma unroll
        for (int i = 0; i < 4; i++) dst[tid + 256 * i] = src[tid + 256 * i];
    }
    __syncthreads();

    {
        float4 bb = *reinterpret_cast<const float4*>(b2 + j0);
        acc[0] = make_float2(bb.x, bb.x); acc[1] = make_float2(bb.y, bb.y);
        acc[2] = make_float2(bb.z, bb.z); acc[3] = make_float2(bb.w, bb.w);
        #pragma unroll 8
        for (int k = 0; k < IDIM; k++) {
            float2 a2 = *reinterpret_cast<float2*>(&S->AT[k][2 * eg]);
            float4 w4 = *reinterpret_cast<float4*>(&S->Wsh[k * IDIM + j0]);
            acc[0] = ffma2(a2, make_float2(w4.x, w4.x), acc[0]);
            acc[1] = ffma2(a2, make_float2(w4.y, w4.y), acc[1]);
            acc[2] = ffma2(a2, make_float2(w4.z, w4.z), acc[2]);
            acc[3] = ffma2(a2, make_float2(w4.w, w4.w), acc[3]);
        }
    }

    #pragma unroll
    for (int half = 0; half < 2; half++) {
        float v[4];
        v[0] = gelu_exact(half ? acc[0].y : acc[0].x);
        v[1] = gelu_exact(half ? acc[1].y : acc[1].x);
        v[2] = gelu_exact(half ? acc[2].y : acc[2].x);
        v[3] = gelu_exact(half ? acc[3].y : acc[3].x);
        __nv_bfloat16 h[4], l[4];
        #pragma unroll
        for (int f = 0; f < 4; f++) {
            h[f] = __float2bfloat16(v[f]);
            l[f] = __float2bfloat16(v[f] - __bfloat162float(h[f]));
        }
        size_t rb = (size_t)(e0 + 2 * eg + half) * K2;
        uint2 hb = *reinterpret_cast<uint2*>(h);
        uint2 lb = *reinterpret_cast<uint2*>(l);
        *reinterpret_cast<uint2*>(&g_a2[rb +       j0]) = hb;
        *reinterpret_cast<uint2*>(&g_a2[rb +  64 + j0]) = hb;
        *reinterpret_cast<uint2*>(&g_a2[rb + 128 + j0]) = lb;
    }
}

// ---------------- kernel 2: embedding gather ----------------
#define EMBED_BLOCKS 1184
__global__ void __launch_bounds__(256) k_embed(const int* __restrict__ ids,
                                               const float* __restrict__ wte,
                                               float* __restrict__ out) {
    const int lane   = threadIdx.x & 31;
    const int warp   = (blockIdx.x * blockDim.x + threadIdx.x) >> 5;
    const int nwarps = (EMBED_BLOCKS * 256) >> 5;

    for (int row = warp; row < NROWS; row += nwarps) {
        if (g_winner[row] >= 0) continue;       // overwritten by gemm epilogue
        int id = ids[row];
        id = max(0, min(id, VV - 1));
        const float4* __restrict__ src = reinterpret_cast<const float4*>(wte + (size_t)id * HH);
        float4*       __restrict__ dst = reinterpret_cast<float4*>(out + (size_t)row * HH);
        #pragma unroll
        for (int h = 0; h < 2; h++) {
            float4 v[8];
            #pragma unroll
            for (int i = 0; i < 8; i++) v[i] = src[lane + 32 * (8 * h + i)];
            #pragma unroll
            for (int i = 0; i < 8; i++) __stcs(&dst[lane + 32 * (8 * h + i)], v[i]);
        }
    }
}

// ---------------- kernel 3: pipelined HMMA GEMM [count x 192] @ [192 x 2048] ----------
// Tile 128m x 128n x 192k. Double-buffered ldmatrix fragments: step k+1's loads
// issue before step k's MMAs retire, hiding LDSM latency under HMMA issue.
#define GS_STRIDE 200
#define GEMM_SMEM (2 * 128 * GS_STRIDE * 2)   // 102400 B
extern __shared__ __nv_bfloat16 gsm2[];

__global__ void __launch_bounds__(256, 2) k_gemm_mma(const float* __restrict__ bout,
                                                     float* __restrict__ out) {
    const int count = g_count;
    const int m0 = blockIdx.y * 128;
    if (m0 >= count) return;
    const int n0 = blockIdx.x * 128;
    const int tid = threadIdx.x;

    __nv_bfloat16* As = gsm2;
    __nv_bfloat16* Bs = gsm2 + 128 * GS_STRIDE;

    // stage A (gathered rows) and B: thread t -> row t>>1, half t&1, 12 uint4 each
    {
        int r = tid >> 1, h = tid & 1;
        int row = m0 + r;
        const uint4* srcA = nullptr;
        if (row < count)
            srcA = reinterpret_cast<const uint4*>(g_a2 + (size_t)g_widx[row] * K2) + h * 12;
        uint4* dstA = reinterpret_cast<uint4*>(As + r * GS_STRIDE + h * 96);
        const uint4* srcB = reinterpret_cast<const uint4*>(g_b2T + (size_t)(n0 + r) * K2) + h * 12;
        uint4* dstB = reinterpret_cast<uint4*>(Bs + r * GS_STRIDE + h * 96);
        #pragma unroll
        for (int c = 0; c < 12; c++) {
            dstA[c] = srcA ? srcA[c] : make_uint4(0u, 0u, 0u, 0u);
            dstB[c] = srcB[c];
        }
    }
    __syncthreads();

    const int wid  = tid >> 5;
    const int lane = tid & 31;
    const int mg   = wid & 3;        // m-group: rows mg*32 .. +31
    const int ng   = wid >> 2;       // n-group: cols ng*64 .. +63

    uint32_t aAddr = smem_u32(As) +
        (uint32_t)(((mg * 32 + (lane & 15)) * GS_STRIDE + (lane >> 4) * 8) * 2);
    uint32_t bAddr = smem_u32(Bs) +
        (uint32_t)(((ng * 64 + (lane & 7) + ((lane >> 4) << 3)) * GS_STRIDE +
                    (((lane >> 3) & 1) << 3)) * 2);

    float acc[2][8][4];
    #pragma unroll
    for (int am = 0; am < 2; am++)
        #pragma unroll
        for (int ns = 0; ns < 8; ns++)
            #pragma unroll
            for (int c = 0; c < 4; c++) acc[am][ns][c] = 0.f;

    // double-buffered fragments
    uint32_t fA[2][2][4];     // [buf][am][regs]
    uint32_t fB[2][4][4];     // [buf][pair][regs]

    #define LOAD_STEP(buf, ks) do {                                             \
        uint32_t _a = aAddr + (uint32_t)(ks) * 32;                              \
        uint32_t _b = bAddr + (uint32_t)(ks) * 32;                              \
        ldm_x4(fA[buf][0], _a);                                                 \
        ldm_x4(fA[buf][1], _a + 16 * GS_STRIDE * 2);                            \
        ldm_x4(fB[buf][0], _b);                                                 \
        ldm_x4(fB[buf][1], _b + 16 * GS_STRIDE * 2);                            \
        ldm_x4(fB[buf][2], _b + 32 * GS_STRIDE * 2);                            \
        ldm_x4(fB[buf][3], _b + 48 * GS_STRIDE * 2);                            \
    } while (0)

    #define MMA_STEP(buf) do {                                                  \
        _Pragma("unroll")                                                       \
        for (int p = 0; p < 4; p++) {                                           \
            mma16816(acc[0][2 * p],     fA[buf][0], fB[buf][p][0], fB[buf][p][1]); \
            mma16816(acc[0][2 * p + 1], fA[buf][0], fB[buf][p][2], fB[buf][p][3]); \
            mma16816(acc[1][2 * p],     fA[buf][1], fB[buf][p][0], fB[buf][p][1]); \
            mma16816(acc[1][2 * p + 1], fA[buf][1], fB[buf][p][2], fB[buf][p][3]); \
        }                                                                       \
    } while (0)

    LOAD_STEP(0, 0);
    #pragma unroll
    for (int ks = 0; ks < K2 / 16; ks += 2) {      // 12 steps, 6 unrolled pairs
        LOAD_STEP(1, ks + 1);                      // prefetch odd step
        MMA_STEP(0);
        if (ks + 2 < K2 / 16) LOAD_STEP(0, ks + 2); // prefetch next even step
        MMA_STEP(1);
    }

    // epilogue: scatter rows via g_slot, add bias
    #pragma unroll
    for (int am = 0; am < 2; am++) {
        int r = m0 + mg * 32 + am * 16 + (lane >> 2);
        int s0 = (r     < count) ? g_slot[r]     : -1;
        int s1 = (r + 8 < count) ? g_slot[r + 8] : -1;
        #pragma unroll
        for (int ns = 0; ns < 8; ns++) {
            int col = n0 + ng * 64 + ns * 8 + (lane & 3) * 2;
            float2 bv = *reinterpret_cast<const float2*>(bout + col);
            if (s0 >= 0) {
                float2 v = make_float2(acc[am][ns][0] + bv.x, acc[am][ns][1] + bv.y);
                *reinterpret_cast<float2*>(out + (size_t)s0 * HH + col) = v;
            }
            if (s1 >= 0) {
                float2 v = make_float2(acc[am][ns][2] + bv.x, acc[am][ns][3] + bv.y);
                *reinterpret_cast<float2*>(out + (size_t)s1 * HH + col) = v;
            }
        }
    }
}

// ---------------- one-time smem opt-in ----------------
namespace {
struct HxInit {
    HxInit() {
        cudaFuncSetAttribute(k_gemm_mma, cudaFuncAttributeMaxDynamicSharedMemorySize, GEMM_SMEM);
    }
};
HxInit hx_init_;
}

// ---------------- launcher: 3 nodes, single stream ----------------
extern "C" void kernel_launch(void* const* d_in, const int* in_sizes, int n_in,
                              void* d_out, int out_size) {
    const int*   input_ids = (const int*)  d_in[0];
    const float* lc        = (const float*)d_in[1];
    const int*   pos_b     = (const int*)  d_in[2];
    const int*   pos_s     = (const int*)  d_in[3];
    const float* wte       = (const float*)d_in[4];
    const float* W0        = (const float*)d_in[5];
    const float* b0        = (const float*)d_in[6];
    const float* W1        = (const float*)d_in[7];
    const float* b1        = (const float*)d_in[8];
    const float* W2        = (const float*)d_in[9];
    const float* b2        = (const float*)d_in[10];
    const float* Wout      = (const float*)d_in[11];
    const float* bout      = (const float*)d_in[12];
    float* out = (float*)d_out;

    // prep (148) + MLP (256) + wsplit (32) fused by block role
    k_auxprep<<<NB_PREP + 256 + 32, 256>>>(pos_b, pos_s, lc, W0, b0, W1, b1, W2, b2, Wout);
    k_embed<<<EMBED_BLOCKS, 256>>>(input_ids, wte, out);
    k_gemm_mma<<<dim3(HH / 128, NLC / 128), 256, GEMM_SMEM>>>(bout, out);
}

// round 16
// speedup vs baseline: 1.1413x; 1.0410x over previous
#include <cuda_runtime.h>
#include <cuda_bf16.h>
#include <math.h>
#include <stdint.h>

// ---------------- problem dims ----------------
#define BB    4
#define SS    4096
#define HH    2048
#define VV    32000
#define IDIM  64
#define NLC   8192
#define NROWS (BB * SS)          // 16384
#define K2    192                // split-K concat: A=[hi|hi|lo], B=[hi|lo|hi]
#define NB_PREP 148

// ---------------- device scratch ----------------
__device__ int g_winner[NROWS];
__device__ int g_slot[NROWS];
__device__ int g_widx[NROWS];
__device__ int g_count;
__device__ unsigned g_bar1 = 0, g_bar2 = 0;
__device__ int g_prep_done = 0;
__device__ __align__(16) __nv_bfloat16 g_a2 [NLC * K2];   // activations, K-concat split
__device__ __align__(16) __nv_bfloat16 g_b2T[HH * K2];    // Wout^T, K-concat split, [n][k]

// ---------------- helpers ----------------
__device__ __forceinline__ float gelu_exact(float x) {
    return 0.5f * x * (1.0f + erff(x * 0.70710678118654752440f));
}
__device__ __forceinline__ float2 ffma2(float2 a, float2 b, float2 c) {
    unsigned long long ra, rb, rc, rd;
    ra = *reinterpret_cast<unsigned long long*>(&a);
    rb = *reinterpret_cast<unsigned long long*>(&b);
    rc = *reinterpret_cast<unsigned long long*>(&c);
    asm("fma.rn.f32x2 %0, %1, %2, %3;" : "=l"(rd) : "l"(ra), "l"(rb), "l"(rc));
    return *reinterpret_cast<float2*>(&rd);
}
__device__ __forceinline__ uint32_t smem_u32(const void* p) {
    uint32_t a;
    asm("{ .reg .u64 t; cvta.to.shared.u64 t, %1; cvt.u32.u64 %0, t; }" : "=r"(a) : "l"(p));
    return a;
}
__device__ __forceinline__ void ldm_x4(uint32_t* r, uint32_t addr) {
    asm volatile("ldmatrix.sync.aligned.m8n8.x4.shared.b16 {%0,%1,%2,%3}, [%4];"
        : "=r"(r[0]), "=r"(r[1]), "=r"(r[2]), "=r"(r[3]) : "r"(addr));
}
__device__ __forceinline__ void mma16816(float* c, const uint32_t* a, uint32_t b0, uint32_t b1) {
    asm volatile("mma.sync.aligned.m16n8k16.row.col.f32.bf16.bf16.f32 "
        "{%0,%1,%2,%3}, {%4,%5,%6,%7}, {%8,%9}, {%0,%1,%2,%3};"
        : "+f"(c[0]), "+f"(c[1]), "+f"(c[2]), "+f"(c[3])
        : "r"(a[0]), "r"(a[1]), "r"(a[2]), "r"(a[3]), "r"(b0), "r"(b1));
}

// grid barrier among the NB_PREP prep-role blocks (bids 0..147, wave-1 resident)
__device__ __forceinline__ void grid_bar(unsigned* bar) {
    __syncthreads();
    __threadfence();
    if (threadIdx.x == 0) {
        atomicAdd(bar, 1u);
        while (atomicAdd(bar, 0u) < NB_PREP) { }
    }
    __syncthreads();
    __threadfence();
}

// ---------------- kernel 1: fused prep (bids 0-147) + MLP (148-403) + wsplit (404-435) ----
#define MLP_E 32
struct MlpSmem { float AT[IDIM][MLP_E + 2]; float Wsh[IDIM * IDIM]; float xsh[MLP_E]; };
struct WspSmem { float tile[IDIM][65]; };

__global__ void __launch_bounds__(256) k_auxprep(
                      const int* __restrict__ pos_b, const int* __restrict__ pos_s,
                      const float* __restrict__ lc,
                      const float* __restrict__ W0, const float* __restrict__ b0,
                      const float* __restrict__ W1, const float* __restrict__ b1,
                      const float* __restrict__ W2, const float* __restrict__ b2,
                      const float* __restrict__ Wout) {
    __shared__ __align__(16) char shraw[sizeof(MlpSmem)];
    const int tid = threadIdx.x;
    const int bid = blockIdx.x;

    if (bid < NB_PREP) {
        // ===== PREP role: init + winner + compact (resident-grid barrier) =====
        const int gt = bid * 256 + tid;

        if (gt < NROWS) g_winner[gt] = -1;
        if (gt == 0) g_count = 0;
        grid_bar(&g_bar1);

        if (gt < NLC) {
            int slot = pos_b[gt] * SS + pos_s[gt];
            atomicMax(&g_winner[slot], gt);     // JAX scatter: last update wins
        }
        grid_bar(&g_bar2);

        if (gt < NROWS) {
            int w = g_winner[gt];
            if (w >= 0) {
                int p = atomicAdd(&g_count, 1);
                g_slot[p] = gt;
                g_widx[p] = w;
            }
        }

        // self-reset for deterministic graph replay
        __syncthreads();
        if (tid == 0) {
            int v = atomicAdd(&g_prep_done, 1);
            if (v == NB_PREP - 1) {
                g_bar1 = 0; g_bar2 = 0; g_prep_done = 0;
                __threadfence();
            }
        }
        return;
    }

    if (bid >= NB_PREP + 256) {
        // ===== WSPLIT role: coalesced Wout split+transpose via smem tile =====
        WspSmem* S = reinterpret_cast<WspSmem*>(shraw);
        const int n0 = (bid - NB_PREP - 256) * 64;

        {
            int r = tid >> 2, q = tid & 3;
            #pragma unroll
            for (int i = 0; i < 4; i++) {
                float4 v = *reinterpret_cast<const float4*>(Wout + r * HH + n0 + (q + 4 * i) * 4);
                int c = (q + 4 * i) * 4;
                S->tile[r][c + 0] = v.x; S->tile[r][c + 1] = v.y;
                S->tile[r][c + 2] = v.z; S->tile[r][c + 3] = v.w;
            }
        }
        __syncthreads();

        {
            int nl = tid >> 2, kq = (tid & 3) * 16;
            __nv_bfloat16 h[16], l[16];
            #pragma unroll
            for (int j = 0; j < 16; j++) {
                float w = S->tile[kq + j][nl];
                h[j] = __float2bfloat16(w);
                l[j] = __float2bfloat16(w - __bfloat162float(h[j]));
            }
            size_t rb = (size_t)(n0 + nl) * K2;
            uint4* ph = reinterpret_cast<uint4*>(h);
            uint4* pl = reinterpret_cast<uint4*>(l);
            // [0,64)=hi, [64,128)=lo, [128,192)=hi  (pairs with A's hi,hi,lo)
            *reinterpret_cast<uint4*>(&g_b2T[rb +       kq])     = ph[0];
            *reinterpret_cast<uint4*>(&g_b2T[rb +       kq + 8]) = ph[1];
            *reinterpret_cast<uint4*>(&g_b2T[rb +  64 + kq])     = pl[0];
            *reinterpret_cast<uint4*>(&g_b2T[rb +  64 + kq + 8]) = pl[1];
            *reinterpret_cast<uint4*>(&g_b2T[rb + 128 + kq])     = ph[0];
            *reinterpret_cast<uint4*>(&g_b2T[rb + 128 + kq + 8]) = ph[1];
        }
        return;
    }

    // ===== MLP role: 1->64->64->64, emit K-concat split-bf16 [hi | hi | lo] =====
    MlpSmem* S = reinterpret_cast<MlpSmem*>(shraw);
    const int f4  = tid & 15;
    const int eg  = tid >> 4;
    const int j0  = f4 * 4;
    const int e0  = (bid - NB_PREP) * MLP_E;

    if (tid < MLP_E) S->xsh[tid] = lc[e0 + tid];
    {
        const float4* src = reinterpret_cast<const float4*>(W1);
        float4* dst = reinterpret_cast<float4*>(S->Wsh);
        #pragma unroll
        for (int i = 0; i < 4; i++) dst[tid + 256 * i] = src[tid + 256 * i];
    }
    __syncthreads();

    #pragma unroll
    for (int r = 0; r < 4; r++) {
        int k = j0 + r;
        float w = W0[k], b = b0[k];
        float v0 = gelu_exact(fmaf(S->xsh[2 * eg],     w, b));
        float v1 = gelu_exact(fmaf(S->xsh[2 * eg + 1], w, b));
        *reinterpret_cast<float2*>(&S->AT[k][2 * eg]) = make_float2(v0, v1);
    }
    __syncthreads();

    float2 acc[4];
    {
        float4 bb = *reinterpret_cast<const float4*>(b1 + j0);
        acc[0] = make_float2(bb.x, bb.x); acc[1] = make_float2(bb.y, bb.y);
        acc[2] = make_float2(bb.z, bb.z); acc[3] = make_float2(bb.w, bb.w);
        #pragma unroll 8
        for (int k = 0; k < IDIM; k++) {
            float2 a2 = *reinterpret_cast<float2*>(&S->AT[k][2 * eg]);
            float4 w4 = *reinterpret_cast<float4*>(&S->Wsh[k * IDIM + j0]);
            acc[0] = ffma2(a2, make_float2(w4.x, w4.x), acc[0]);
            acc[1] = ffma2(a2, make_float2(w4.y, w4.y), acc[1]);
            acc[2] = ffma2(a2, make_float2(w4.z, w4.z), acc[2]);
            acc[3] = ffma2(a2, make_float2(w4.w, w4.w), acc[3]);
        }
    }
    __syncthreads();

    #pragma unroll
    for (int f = 0; f < 4; f++) {
        *reinterpret_cast<float2*>(&S->AT[j0 + f][2 * eg]) =
            make_float2(gelu_exact(acc[f].x), gelu_exact(acc[f].y));
    }
    {
        const float4* src = reinterpret_cast<const float4*>(W2);
        float4* dst = reinterpret_cast<float4*>(S->Wsh);
        #pragma unroll
        for (int i = 0; i < 4; i++) dst[tid + 256 * i] = src[tid + 256 * i];
    }
    __syncthreads();

    {
        float4 bb = *reinterpret_cast<const float4*>(b2 + j0);
        acc[0] = make_float2(bb.x, bb.x); acc[1] = make_float2(bb.y, bb.y);
        acc[2] = make_float2(bb.z, bb.z); acc[3] = make_float2(bb.w, bb.w);
        #pragma unroll 8
        for (int k = 0; k < IDIM; k++) {
            float2 a2 = *reinterpret_cast<float2*>(&S->AT[k][2 * eg]);
            float4 w4 = *reinterpret_cast<float4*>(&S->Wsh[k * IDIM + j0]);
            acc[0] = ffma2(a2, make_float2(w4.x, w4.x), acc[0]);
            acc[1] = ffma2(a2, make_float2(w4.y, w4.y), acc[1]);
            acc[2] = ffma2(a2, make_float2(w4.z, w4.z), acc[2]);
            acc[3] = ffma2(a2, make_float2(w4.w, w4.w), acc[3]);
        }
    }

    #pragma unroll
    for (int half = 0; half < 2; half++) {
        float v[4];
        v[0] = gelu_exact(half ? acc[0].y : acc[0].x);
        v[1] = gelu_exact(half ? acc[1].y : acc[1].x);
        v[2] = gelu_exact(half ? acc[2].y : acc[2].x);
        v[3] = gelu_exact(half ? acc[3].y : acc[3].x);
        __nv_bfloat16 h[4], l[4];
        #pragma unroll
        for (int f = 0; f < 4; f++) {
            h[f] = __float2bfloat16(v[f]);
            l[f] = __float2bfloat16(v[f] - __bfloat162float(h[f]));
        }
        size_t rb = (size_t)(e0 + 2 * eg + half) * K2;
        uint2 hb = *reinterpret_cast<uint2*>(h);
        uint2 lb = *reinterpret_cast<uint2*>(l);
        *reinterpret_cast<uint2*>(&g_a2[rb +       j0]) = hb;
        *reinterpret_cast<uint2*>(&g_a2[rb +  64 + j0]) = hb;
        *reinterpret_cast<uint2*>(&g_a2[rb + 128 + j0]) = lb;
    }
}

// ---------------- kernel 2: MEGA — HMMA gemm tile + per-block embed tail ----------
// Grid 1024 = 64 m-tiles x 16 n-tiles. Each block: (a) gemm 128x128 tile with
// scatter epilogue (skipped if m0 >= count), (b) copy its own 16 embedding rows
// (16384 = 1024*16). Early-finishing / pure-embed blocks saturate DRAM while
// tensor-phase blocks stall on LDSM — overlap is structural, not stream-based.
#define GS_STRIDE 200
#define GEMM_SMEM (2 * 128 * GS_STRIDE * 2)   // 102400 B
#define GEMM_GRID ((HH / 128) * (NLC / 128))  // 1024
#define EMB_PER_BLK (NROWS / GEMM_GRID)       // 16
extern __shared__ __nv_bfloat16 gsm2[];

__global__ void __launch_bounds__(256, 2) k_main(const int* __restrict__ ids,
                                                 const float* __restrict__ wte,
                                                 const float* __restrict__ bout,
                                                 float* __restrict__ out) {
    const int bid = blockIdx.x;
    const int tid = threadIdx.x;
    const int count = g_count;
    const int m0 = (bid >> 4) * 128;
    const int n0 = (bid & 15) * 128;

    if (m0 < count) {
        // ================= GEMM phase =================
        __nv_bfloat16* As = gsm2;
        __nv_bfloat16* Bs = gsm2 + 128 * GS_STRIDE;

        // stage A (gathered rows) and B: thread t -> row t>>1, half t&1, 12 uint4 each
        {
            int r = tid >> 1, h = tid & 1;
            int row = m0 + r;
            const uint4* srcA = nullptr;
            if (row < count)
                srcA = reinterpret_cast<const uint4*>(g_a2 + (size_t)g_widx[row] * K2) + h * 12;
            uint4* dstA = reinterpret_cast<uint4*>(As + r * GS_STRIDE + h * 96);
            const uint4* srcB = reinterpret_cast<const uint4*>(g_b2T + (size_t)(n0 + r) * K2) + h * 12;
            uint4* dstB = reinterpret_cast<uint4*>(Bs + r * GS_STRIDE + h * 96);
            #pragma unroll
            for (int c = 0; c < 12; c++) {
                dstA[c] = srcA ? srcA[c] : make_uint4(0u, 0u, 0u, 0u);
                dstB[c] = srcB[c];
            }
        }
        __syncthreads();

        const int wid  = tid >> 5;
        const int lane = tid & 31;
        const int mg   = wid & 3;        // m-group: rows mg*32 .. +31
        const int ng   = wid >> 2;       // n-group: cols ng*64 .. +63

        uint32_t aAddr = smem_u32(As) +
            (uint32_t)(((mg * 32 + (lane & 15)) * GS_STRIDE + (lane >> 4) * 8) * 2);
        uint32_t bAddr = smem_u32(Bs) +
            (uint32_t)(((ng * 64 + (lane & 7) + ((lane >> 4) << 3)) * GS_STRIDE +
                        (((lane >> 3) & 1) << 3)) * 2);

        float acc[2][8][4];
        #pragma unroll
        for (int am = 0; am < 2; am++)
            #pragma unroll
            for (int ns = 0; ns < 8; ns++)
                #pragma unroll
                for (int c = 0; c < 4; c++) acc[am][ns][c] = 0.f;

        // single-buffered fragments, fully unrolled: ptxas schedules next-step
        // LDSMs under current MMAs within the 128-reg budget (no spills)
        #pragma unroll
        for (int ks = 0; ks < K2 / 16; ks++) {
            uint32_t aF0[4], aF1[4], bF[4][4];
            ldm_x4(aF0, aAddr + ks * 32);
            ldm_x4(aF1, aAddr + ks * 32 + 16 * GS_STRIDE * 2);
            #pragma unroll
            for (int p = 0; p < 4; p++) ldm_x4(bF[p], bAddr + ks * 32 + p * 16 * GS_STRIDE * 2);
            #pragma unroll
            for (int p = 0; p < 4; p++) {
                mma16816(acc[0][2 * p],     aF0, bF[p][0], bF[p][1]);
                mma16816(acc[0][2 * p + 1], aF0, bF[p][2], bF[p][3]);
                mma16816(acc[1][2 * p],     aF1, bF[p][0], bF[p][1]);
                mma16816(acc[1][2 * p + 1], aF1, bF[p][2], bF[p][3]);
            }
        }

        // epilogue: scatter rows via g_slot, add bias
        #pragma unroll
        for (int am = 0; am < 2; am++) {
            int r = m0 + mg * 32 + am * 16 + (lane >> 2);
            int s0 = (r     < count) ? g_slot[r]     : -1;
            int s1 = (r + 8 < count) ? g_slot[r + 8] : -1;
            #pragma unroll
            for (int ns = 0; ns < 8; ns++) {
                int col = n0 + ng * 64 + ns * 8 + (lane & 3) * 2;
                float2 bv = *reinterpret_cast<const float2*>(bout + col);
                if (s0 >= 0) {
                    float2 v = make_float2(acc[am][ns][0] + bv.x, acc[am][ns][1] + bv.y);
                    *reinterpret_cast<float2*>(out + (size_t)s0 * HH + col) = v;
                }
                if (s1 >= 0) {
                    float2 v = make_float2(acc[am][ns][2] + bv.x, acc[am][ns][3] + bv.y);
                    *reinterpret_cast<float2*>(out + (size_t)s1 * HH + col) = v;
                }
            }
        }
    }

    // ================= EMBED tail: this block's 16 rows =================
    {
        const int lane = tid & 31;
        const int wid  = tid >> 5;
        #pragma unroll
        for (int e = 0; e < EMB_PER_BLK / 8; e++) {      // 2 rows per warp
            int row = bid * EMB_PER_BLK + e * 8 + wid;
            if (g_winner[row] >= 0) continue;            // written by gemm epilogue
            int id = ids[row];
            id = max(0, min(id, VV - 1));
            const float4* __restrict__ src = reinterpret_cast<const float4*>(wte + (size_t)id * HH);
            float4*       __restrict__ dst = reinterpret_cast<float4*>(out + (size_t)row * HH);
            #pragma unroll
            for (int h = 0; h < 2; h++) {
                float4 v[8];
                #pragma unroll
                for (int i = 0; i < 8; i++) v[i] = src[lane + 32 * (8 * h + i)];
                #pragma unroll
                for (int i = 0; i < 8; i++) __stcs(&dst[lane + 32 * (8 * h + i)], v[i]);
            }
        }
    }
}

// ---------------- one-time smem opt-in ----------------
namespace {
struct HxInit {
    HxInit() {
        cudaFuncSetAttribute(k_main, cudaFuncAttributeMaxDynamicSharedMemorySize, GEMM_SMEM);
    }
};
HxInit hx_init_;
}

// ---------------- launcher: 2 nodes, single stream ----------------
extern "C" void kernel_launch(void* const* d_in, const int* in_sizes, int n_in,
                              void* d_out, int out_size) {
    const int*   input_ids = (const int*)  d_in[0];
    const float* lc        = (const float*)d_in[1];
    const int*   pos_b     = (const int*)  d_in[2];
    const int*   pos_s     = (const int*)  d_in[3];
    const float* wte       = (const float*)d_in[4];
    const float* W0        = (const float*)d_in[5];
    const float* b0        = (const float*)d_in[6];
    const float* W1        = (const float*)d_in[7];
    const float* b1        = (const float*)d_in[8];
    const float* W2        = (const float*)d_in[9];
    const float* b2        = (const float*)d_in[10];
    const float* Wout      = (const float*)d_in[11];
    const float* bout      = (const float*)d_in[12];
    float* out = (float*)d_out;

    // prep (148) + MLP (256) + wsplit (32) fused by block role
    k_auxprep<<<NB_PREP + 256 + 32, 256>>>(pos_b, pos_s, lc, W0, b0, W1, b1, W2, b2, Wout);
    // gemm + embed fused: every block does a gemm tile then its 16 embed rows
    k_main<<<GEMM_GRID, 256, GEMM_SMEM>>>(input_ids, wte, bout, out);
}

// round 17
// speedup vs baseline: 1.2127x; 1.0625x over previous
#include <cuda_runtime.h>
#include <cuda_bf16.h>
#include <math.h>
#include <stdint.h>

// ---------------- problem dims ----------------
#define BB    4
#define SS    4096
#define HH    2048
#define VV    32000
#define IDIM  64
#define NLC   8192
#define NROWS (BB * SS)          // 16384
#define K2    192                // split-K concat: A=[hi|hi|lo], B=[hi|lo|hi]
#define NB_PREP 148

// ---------------- device scratch ----------------
__device__ int g_winner[NROWS];
__device__ int g_slot[NROWS];
__device__ int g_widx[NROWS];
__device__ int g_count;
__device__ unsigned g_bar1 = 0, g_bar2 = 0;
__device__ int g_prep_done = 0;
__device__ __align__(16) __nv_bfloat16 g_a2 [NLC * K2];   // activations, K-concat split
__device__ __align__(16) __nv_bfloat16 g_b2T[HH * K2];    // Wout^T, K-concat split, [n][k]

// ---------------- helpers ----------------
__device__ __forceinline__ float gelu_exact(float x) {
    return 0.5f * x * (1.0f + erff(x * 0.70710678118654752440f));
}
__device__ __forceinline__ float2 ffma2(float2 a, float2 b, float2 c) {
    unsigned long long ra, rb, rc, rd;
    ra = *reinterpret_cast<unsigned long long*>(&a);
    rb = *reinterpret_cast<unsigned long long*>(&b);
    rc = *reinterpret_cast<unsigned long long*>(&c);
    asm("fma.rn.f32x2 %0, %1, %2, %3;" : "=l"(rd) : "l"(ra), "l"(rb), "l"(rc));
    return *reinterpret_cast<float2*>(&rd);
}
__device__ __forceinline__ uint32_t smem_u32(const void* p) {
    uint32_t a;
    asm("{ .reg .u64 t; cvta.to.shared.u64 t, %1; cvt.u32.u64 %0, t; }" : "=r"(a) : "l"(p));
    return a;
}
__device__ __forceinline__ void ldm_x4(uint32_t* r, uint32_t addr) {
    asm volatile("ldmatrix.sync.aligned.m8n8.x4.shared.b16 {%0,%1,%2,%3}, [%4];"
        : "=r"(r[0]), "=r"(r[1]), "=r"(r[2]), "=r"(r[3]) : "r"(addr));
}
__device__ __forceinline__ void mma16816(float* c, const uint32_t* a, uint32_t b0, uint32_t b1) {
    asm volatile("mma.sync.aligned.m16n8k16.row.col.f32.bf16.bf16.f32 "
        "{%0,%1,%2,%3}, {%4,%5,%6,%7}, {%8,%9}, {%0,%1,%2,%3};"
        : "+f"(c[0]), "+f"(c[1]), "+f"(c[2]), "+f"(c[3])
        : "r"(a[0]), "r"(a[1]), "r"(a[2]), "r"(a[3]), "r"(b0), "r"(b1));
}

// grid barrier among the NB_PREP prep-role blocks (bids 0..147, wave-1 resident)
__device__ __forceinline__ void grid_bar(unsigned* bar) {
    __syncthreads();
    __threadfence();
    if (threadIdx.x == 0) {
        atomicAdd(bar, 1u);
        while (atomicAdd(bar, 0u) < NB_PREP) { }
    }
    __syncthreads();
    __threadfence();
}

// ---------------- kernel 1: fused prep (bids 0-147) + MLP (148-403) + wsplit (404-435) ----
#define MLP_E 32
struct MlpSmem { float AT[IDIM][MLP_E + 2]; float Wsh[IDIM * IDIM]; float xsh[MLP_E]; };
struct WspSmem { float tile[IDIM][65]; };

__global__ void __launch_bounds__(256) k_auxprep(
                      const int* __restrict__ pos_b, const int* __restrict__ pos_s,
                      const float* __restrict__ lc,
                      const float* __restrict__ W0, const float* __restrict__ b0,
                      const float* __restrict__ W1, const float* __restrict__ b1,
                      const float* __restrict__ W2, const float* __restrict__ b2,
                      const float* __restrict__ Wout) {
    __shared__ __align__(16) char shraw[sizeof(MlpSmem)];
    const int tid = threadIdx.x;
    const int bid = blockIdx.x;

    if (bid < NB_PREP) {
        // ===== PREP role: init + winner + compact (resident-grid barrier) =====
        const int gt = bid * 256 + tid;

        if (gt < NROWS) g_winner[gt] = -1;
        if (gt == 0) g_count = 0;
        grid_bar(&g_bar1);

        if (gt < NLC) {
            int slot = pos_b[gt] * SS + pos_s[gt];
            atomicMax(&g_winner[slot], gt);     // JAX scatter: last update wins
        }
        grid_bar(&g_bar2);

        if (gt < NROWS) {
            int w = g_winner[gt];
            if (w >= 0) {
                int p = atomicAdd(&g_count, 1);
                g_slot[p] = gt;
                g_widx[p] = w;
            }
        }

        // self-reset for deterministic graph replay
        __syncthreads();
        if (tid == 0) {
            int v = atomicAdd(&g_prep_done, 1);
            if (v == NB_PREP - 1) {
                g_bar1 = 0; g_bar2 = 0; g_prep_done = 0;
                __threadfence();
            }
        }
        return;
    }

    if (bid >= NB_PREP + 256) {
        // ===== WSPLIT role: coalesced Wout split+transpose via smem tile =====
        WspSmem* S = reinterpret_cast<WspSmem*>(shraw);
        const int n0 = (bid - NB_PREP - 256) * 64;

        {
            int r = tid >> 2, q = tid & 3;
            #pragma unroll
            for (int i = 0; i < 4; i++) {
                float4 v = *reinterpret_cast<const float4*>(Wout + r * HH + n0 + (q + 4 * i) * 4);
                int c = (q + 4 * i) * 4;
                S->tile[r][c + 0] = v.x; S->tile[r][c + 1] = v.y;
                S->tile[r][c + 2] = v.z; S->tile[r][c + 3] = v.w;
            }
        }
        __syncthreads();

        {
            int nl = tid >> 2, kq = (tid & 3) * 16;
            __nv_bfloat16 h[16], l[16];
            #pragma unroll
            for (int j = 0; j < 16; j++) {
                float w = S->tile[kq + j][nl];
                h[j] = __float2bfloat16(w);
                l[j] = __float2bfloat16(w - __bfloat162float(h[j]));
            }
            size_t rb = (size_t)(n0 + nl) * K2;
            uint4* ph = reinterpret_cast<uint4*>(h);
            uint4* pl = reinterpret_cast<uint4*>(l);
            // [0,64)=hi, [64,128)=lo, [128,192)=hi  (pairs with A's hi,hi,lo)
            *reinterpret_cast<uint4*>(&g_b2T[rb +       kq])     = ph[0];
            *reinterpret_cast<uint4*>(&g_b2T[rb +       kq + 8]) = ph[1];
            *reinterpret_cast<uint4*>(&g_b2T[rb +  64 + kq])     = pl[0];
            *reinterpret_cast<uint4*>(&g_b2T[rb +  64 + kq + 8]) = pl[1];
            *reinterpret_cast<uint4*>(&g_b2T[rb + 128 + kq])     = ph[0];
            *reinterpret_cast<uint4*>(&g_b2T[rb + 128 + kq + 8]) = ph[1];
        }
        return;
    }

    // ===== MLP role: 1->64->64->64, emit K-concat split-bf16 [hi | hi | lo] =====
    MlpSmem* S = reinterpret_cast<MlpSmem*>(shraw);
    const int f4  = tid & 15;
    const int eg  = tid >> 4;
    const int j0  = f4 * 4;
    const int e0  = (bid - NB_PREP) * MLP_E;

    if (tid < MLP_E) S->xsh[tid] = lc[e0 + tid];
    {
        const float4* src = reinterpret_cast<const float4*>(W1);
        float4* dst = reinterpret_cast<float4*>(S->Wsh);
        #pragma unroll
        for (int i = 0; i < 4; i++) dst[tid + 256 * i] = src[tid + 256 * i];
    }
    __syncthreads();

    #pragma unroll
    for (int r = 0; r < 4; r++) {
        int k = j0 + r;
        float w = W0[k], b = b0[k];
        float v0 = gelu_exact(fmaf(S->xsh[2 * eg],     w, b));
        float v1 = gelu_exact(fmaf(S->xsh[2 * eg + 1], w, b));
        *reinterpret_cast<float2*>(&S->AT[k][2 * eg]) = make_float2(v0, v1);
    }
    __syncthreads();

    float2 acc[4];
    {
        float4 bb = *reinterpret_cast<const float4*>(b1 + j0);
        acc[0] = make_float2(bb.x, bb.x); acc[1] = make_float2(bb.y, bb.y);
        acc[2] = make_float2(bb.z, bb.z); acc[3] = make_float2(bb.w, bb.w);
        #pragma unroll 8
        for (int k = 0; k < IDIM; k++) {
            float2 a2 = *reinterpret_cast<float2*>(&S->AT[k][2 * eg]);
            float4 w4 = *reinterpret_cast<float4*>(&S->Wsh[k * IDIM + j0]);
            acc[0] = ffma2(a2, make_float2(w4.x, w4.x), acc[0]);
            acc[1] = ffma2(a2, make_float2(w4.y, w4.y), acc[1]);
            acc[2] = ffma2(a2, make_float2(w4.z, w4.z), acc[2]);
            acc[3] = ffma2(a2, make_float2(w4.w, w4.w), acc[3]);
        }
    }
    __syncthreads();

    #pragma unroll
    for (int f = 0; f < 4; f++) {
        *reinterpret_cast<float2*>(&S->AT[j0 + f][2 * eg]) =
            make_float2(gelu_exact(acc[f].x), gelu_exact(acc[f].y));
    }
    {
        const float4* src = reinterpret_cast<const float4*>(W2);
        float4* dst = reinterpret_cast<float4*>(S->Wsh);
        #pragma unroll
        for (int i = 0; i < 4; i++) dst[tid + 256 * i] = src[tid + 256 * i];
    }
    __syncthreads();

    {
        float4 bb = *reinterpret_cast<const float4*>(b2 + j0);
        acc[0] = make_float2(bb.x, bb.x); acc[1] = make_float2(bb.y, bb.y);
        acc[2] = make_float2(bb.z, bb.z); acc[3] = make_float2(bb.w, bb.w);
        #pragma unroll 8
        for (int k = 0; k < IDIM; k++) {
            float2 a2 = *reinterpret_cast<float2*>(&S->AT[k][2 * eg]);
            float4 w4 = *reinterpret_cast<float4*>(&S->Wsh[k * IDIM + j0]);
            acc[0] = ffma2(a2, make_float2(w4.x, w4.x), acc[0]);
            acc[1] = ffma2(a2, make_float2(w4.y, w4.y), acc[1]);
            acc[2] = ffma2(a2, make_float2(w4.z, w4.z), acc[2]);
            acc[3] = ffma2(a2, make_float2(w4.w, w4.w), acc[3]);
        }
    }

    #pragma unroll
    for (int half = 0; half < 2; half++) {
        float v[4];
        v[0] = gelu_exact(half ? acc[0].y : acc[0].x);
        v[1] = gelu_exact(half ? acc[1].y : acc[1].x);
        v[2] = gelu_exact(half ? acc[2].y : acc[2].x);
        v[3] = gelu_exact(half ? acc[3].y : acc[3].x);
        __nv_bfloat16 h[4], l[4];
        #pragma unroll
        for (int f = 0; f < 4; f++) {
            h[f] = __float2bfloat16(v[f]);
            l[f] = __float2bfloat16(v[f] - __bfloat162float(h[f]));
        }
        size_t rb = (size_t)(e0 + 2 * eg + half) * K2;
        uint2 hb = *reinterpret_cast<uint2*>(h);
        uint2 lb = *reinterpret_cast<uint2*>(l);
        *reinterpret_cast<uint2*>(&g_a2[rb +       j0]) = hb;
        *reinterpret_cast<uint2*>(&g_a2[rb +  64 + j0]) = hb;
        *reinterpret_cast<uint2*>(&g_a2[rb + 128 + j0]) = lb;
    }
}

// ---------------- kernel 2: MEGA — HMMA gemm tile + per-block embed tail ----------
// Grid 1024 = 64 m-tiles x 16 n-tiles, 512 threads (16 warps). Warp tile 32m x 32n:
// acc = 32 regs, fragments = 16 -> ~90 regs total, no spills, full unroll legal.
// 2 blocks/SM x 512 thr = 1024 threads resident. Embed tail: 1 row per warp.
#define GS_STRIDE 200
#define GEMM_SMEM (2 * 128 * GS_STRIDE * 2)   // 102400 B
#define GEMM_GRID ((HH / 128) * (NLC / 128))  // 1024
#define EMB_PER_BLK (NROWS / GEMM_GRID)       // 16
extern __shared__ __nv_bfloat16 gsm2[];

__global__ void __launch_bounds__(512, 2) k_main(const int* __restrict__ ids,
                                                 const float* __restrict__ wte,
                                                 const float* __restrict__ bout,
                                                 float* __restrict__ out) {
    const int bid = blockIdx.x;
    const int tid = threadIdx.x;
    const int count = g_count;
    const int m0 = (bid >> 4) * 128;
    const int n0 = (bid & 15) * 128;

    if (m0 < count) {
        // ================= GEMM phase =================
        __nv_bfloat16* As = gsm2;
        __nv_bfloat16* Bs = gsm2 + 128 * GS_STRIDE;

        // stage A (gathered rows) and B: thread t -> row t>>2, quarter t&3, 6 uint4 each
        {
            int r = tid >> 2, q = tid & 3;
            int row = m0 + r;
            const uint4* srcA = nullptr;
            if (row < count)
                srcA = reinterpret_cast<const uint4*>(g_a2 + (size_t)g_widx[row] * K2) + q * 6;
            uint4* dstA = reinterpret_cast<uint4*>(As + r * GS_STRIDE + q * 48);
            const uint4* srcB = reinterpret_cast<const uint4*>(g_b2T + (size_t)(n0 + r) * K2) + q * 6;
            uint4* dstB = reinterpret_cast<uint4*>(Bs + r * GS_STRIDE + q * 48);
            #pragma unroll
            for (int c = 0; c < 6; c++) {
                dstA[c] = srcA ? srcA[c] : make_uint4(0u, 0u, 0u, 0u);
                dstB[c] = srcB[c];
            }
        }
        __syncthreads();

        const int wid  = tid >> 5;
        const int lane = tid & 31;
        const int mg   = wid & 3;        // m-group: rows mg*32 .. +31
        const int ng   = wid >> 2;       // n-group: cols ng*32 .. +31

        uint32_t aAddr = smem_u32(As) +
            (uint32_t)(((mg * 32 + (lane & 15)) * GS_STRIDE + (lane >> 4) * 8) * 2);
        uint32_t bAddr = smem_u32(Bs) +
            (uint32_t)(((ng * 32 + (lane & 7) + ((lane >> 4) << 3)) * GS_STRIDE +
                        (((lane >> 3) & 1) << 3)) * 2);

        float acc[2][4][4];
        #pragma unroll
        for (int am = 0; am < 2; am++)
            #pragma unroll
            for (int ns = 0; ns < 4; ns++)
                #pragma unroll
                for (int c = 0; c < 4; c++) acc[am][ns][c] = 0.f;

        // single-buffered fragments, full unroll — fits in ~90 regs, no spills
        #pragma unroll
        for (int ks = 0; ks < K2 / 16; ks++) {
            uint32_t aF0[4], aF1[4], bF0[4], bF1[4];
            ldm_x4(aF0, aAddr + ks * 32);
            ldm_x4(aF1, aAddr + ks * 32 + 16 * GS_STRIDE * 2);
            ldm_x4(bF0, bAddr + ks * 32);
            ldm_x4(bF1, bAddr + ks * 32 + 16 * GS_STRIDE * 2);
            mma16816(acc[0][0], aF0, bF0[0], bF0[1]);
            mma16816(acc[0][1], aF0, bF0[2], bF0[3]);
            mma16816(acc[0][2], aF0, bF1[0], bF1[1]);
            mma16816(acc[0][3], aF0, bF1[2], bF1[3]);
            mma16816(acc[1][0], aF1, bF0[0], bF0[1]);
            mma16816(acc[1][1], aF1, bF0[2], bF0[3]);
            mma16816(acc[1][2], aF1, bF1[0], bF1[1]);
            mma16816(acc[1][3], aF1, bF1[2], bF1[3]);
        }

        // epilogue: scatter rows via g_slot, add bias
        #pragma unroll
        for (int am = 0; am < 2; am++) {
            int r = m0 + mg * 32 + am * 16 + (lane >> 2);
            int s0 = (r     < count) ? g_slot[r]     : -1;
            int s1 = (r + 8 < count) ? g_slot[r + 8] : -1;
            #pragma unroll
            for (int ns = 0; ns < 4; ns++) {
                int col = n0 + ng * 32 + ns * 8 + (lane & 3) * 2;
                float2 bv = *reinterpret_cast<const float2*>(bout + col);
                if (s0 >= 0) {
                    float2 v = make_float2(acc[am][ns][0] + bv.x, acc[am][ns][1] + bv.y);
                    *reinterpret_cast<float2*>(out + (size_t)s0 * HH + col) = v;
                }
                if (s1 >= 0) {
                    float2 v = make_float2(acc[am][ns][2] + bv.x, acc[am][ns][3] + bv.y);
                    *reinterpret_cast<float2*>(out + (size_t)s1 * HH + col) = v;
                }
            }
        }
    }

    // ================= EMBED tail: this block's 16 rows, 1 per warp =================
    {
        const int lane = tid & 31;
        const int wid  = tid >> 5;
        int row = bid * EMB_PER_BLK + wid;
        if (g_winner[row] < 0) {                     // else written by gemm epilogue
            int id = ids[row];
            id = max(0, min(id, VV - 1));
            const float4* __restrict__ src = reinterpret_cast<const float4*>(wte + (size_t)id * HH);
            float4*       __restrict__ dst = reinterpret_cast<float4*>(out + (size_t)row * HH);
            #pragma unroll
            for (int h = 0; h < 2; h++) {
                float4 v[8];
                #pragma unroll
                for (int i = 0; i < 8; i++) v[i] = src[lane + 32 * (8 * h + i)];
                #pragma unroll
                for (int i = 0; i < 8; i++) __stcs(&dst[lane + 32 * (8 * h + i)], v[i]);
            }
        }
    }
}

// ---------------- one-time smem opt-in ----------------
namespace {
struct HxInit {
    HxInit() {
        cudaFuncSetAttribute(k_main, cudaFuncAttributeMaxDynamicSharedMemorySize, GEMM_SMEM);
    }
};
HxInit hx_init_;
}

// ---------------- launcher: 2 nodes, single stream ----------------
extern "C" void kernel_launch(void* const* d_in, const int* in_sizes, int n_in,
                              void* d_out, int out_size) {
    const int*   input_ids = (const int*)  d_in[0];
    const float* lc        = (const float*)d_in[1];
    const int*   pos_b     = (const int*)  d_in[2];
    const int*   pos_s     = (const int*)  d_in[3];
    const float* wte       = (const float*)d_in[4];
    const float* W0        = (const float*)d_in[5];
    const float* b0        = (const float*)d_in[6];
    const float* W1        = (const float*)d_in[7];
    const float* b1        = (const float*)d_in[8];
    const float* W2        = (const float*)d_in[9];
    const float* b2        = (const float*)d_in[10];
    const float* Wout      = (const float*)d_in[11];
    const float* bout      = (const float*)d_in[12];
    float* out = (float*)d_out;

    // prep (148) + MLP (256) + wsplit (32) fused by block role
    k_auxprep<<<NB_PREP + 256 + 32, 256>>>(pos_b, pos_s, lc, W0, b0, W1, b1, W2, b2, Wout);
    // gemm + embed fused: every block does a gemm tile then its 16 embed rows
    k_main<<<GEMM_GRID, 512, GEMM_SMEM>>>(input_ids, wte, bout, out);
}